// round 1
// baseline (speedup 1.0000x reference)
#include <cuda_runtime.h>
#include <cuda_bf16.h>

// Problem constants (fixed-shape benchmark)
#define VOCAB 100000
#define EMB   300
#define BSZ   2048
#define SEQL  200
#define HID   128
#define OUTD  20

#define SPB     8     // samples per block
#define THREADS 256   // 8 warps; warp w handles sample w in gather phase

__global__ __launch_bounds__(THREADS) void fused_embbag_mlp(
    const int*   __restrict__ x,        // [B, L] int32 token ids
    const int*   __restrict__ lengths,  // [B] int32
    const float* __restrict__ emb,      // [VOCAB, EMB]
    const float* __restrict__ W1,       // [EMB, HID]
    const float* __restrict__ b1,       // [HID]
    const float* __restrict__ W2,       // [HID, OUTD]
    const float* __restrict__ b2,       // [OUTD]
    float*       __restrict__ out)      // [B, OUTD]
{
    __shared__ float repT[EMB][SPB];          // transposed rep: 300*8*4 = 9.6 KB
    __shared__ float hpart[2][SPB][HID];      // 8 KB partial sums
    __shared__ float hbuf[SPB][HID];          // 4 KB post-relu hidden

    const int tid  = threadIdx.x;
    const int lane = tid & 31;
    const int w    = tid >> 5;                // warp id = sample within block
    const int b0   = blockIdx.x * SPB;

    // ---------------- Phase 1: embedding-bag sum (per-warp sample) ----------
    {
        const int b = b0 + w;
        const int* xb = x + (size_t)b * SEQL;

        float acc[10];
        #pragma unroll
        for (int k = 0; k < 10; ++k) acc[k] = 0.0f;

        for (int t0 = 0; t0 < SEQL; t0 += 32) {
            const int t = t0 + lane;
            const int myidx = (t < SEQL) ? xb[t] : 0;
            const int cnt = (SEQL - t0) < 32 ? (SEQL - t0) : 32;
            #pragma unroll 4
            for (int tt = 0; tt < cnt; ++tt) {
                const int idx = __shfl_sync(0xffffffffu, myidx, tt);
                const float* row = emb + (size_t)idx * EMB;
                #pragma unroll
                for (int k = 0; k < 10; ++k) {
                    const int d = lane + 32 * k;
                    if (d < EMB) acc[k] += __ldg(row + d);
                }
            }
        }

        const float inv = 1.0f / (float)lengths[b];
        #pragma unroll
        for (int k = 0; k < 10; ++k) {
            const int d = lane + 32 * k;
            if (d < EMB) repT[d][w] = acc[k] * inv;
        }
    }
    __syncthreads();

    // ---------------- Phase 2: h = relu(rep @ W1 + b1) -----------------------
    {
        const int j = tid & (HID - 1);        // output neuron 0..127
        const int c = tid >> 7;               // d-chunk 0/1 (150 each)
        const int d0 = c * 150, d1 = d0 + 150;

        float acc[SPB];
        #pragma unroll
        for (int s = 0; s < SPB; ++s) acc[s] = 0.0f;

        for (int d = d0; d < d1; ++d) {
            const float w1 = __ldg(&W1[(size_t)d * HID + j]);
            // broadcast float4 smem reads: all lanes read the same address
            const float4 r0 = *(const float4*)&repT[d][0];
            const float4 r1 = *(const float4*)&repT[d][4];
            acc[0] += r0.x * w1; acc[1] += r0.y * w1;
            acc[2] += r0.z * w1; acc[3] += r0.w * w1;
            acc[4] += r1.x * w1; acc[5] += r1.y * w1;
            acc[6] += r1.z * w1; acc[7] += r1.w * w1;
        }
        #pragma unroll
        for (int s = 0; s < SPB; ++s) hpart[c][s][j] = acc[s];
    }
    __syncthreads();

    // combine partials + bias + relu
    for (int i = tid; i < SPB * HID; i += THREADS) {
        const int s = i >> 7;
        const int j = i & (HID - 1);
        float v = hpart[0][s][j] + hpart[1][s][j] + __ldg(&b1[j]);
        hbuf[s][j] = v > 0.0f ? v : 0.0f;
    }
    __syncthreads();

    // ---------------- Phase 3: logits = h @ W2 + b2 --------------------------
    if (tid < SPB * OUTD) {
        const int s = tid / OUTD;
        const int o = tid % OUTD;
        float acc = __ldg(&b2[o]);
        #pragma unroll 8
        for (int k = 0; k < HID; ++k)
            acc += hbuf[s][k] * __ldg(&W2[(size_t)k * OUTD + o]);
        out[(size_t)(b0 + s) * OUTD + o] = acc;
    }
}

extern "C" void kernel_launch(void* const* d_in, const int* in_sizes, int n_in,
                              void* d_out, int out_size)
{
    const int*   x       = (const int*)   d_in[0];  // [B,L] int32
    const int*   lengths = (const int*)   d_in[1];  // [B] int32
    const float* emb     = (const float*) d_in[2];  // [VOCAB,EMB]
    const float* W1      = (const float*) d_in[3];  // [EMB,HID]
    const float* b1      = (const float*) d_in[4];  // [HID]
    const float* W2      = (const float*) d_in[5];  // [HID,OUTD]
    const float* b2      = (const float*) d_in[6];  // [OUTD]
    float*       out     = (float*)       d_out;    // [B,OUTD]

    fused_embbag_mlp<<<BSZ / SPB, THREADS>>>(x, lengths, emb, W1, b1, W2, b2, out);
}

// round 2
// speedup vs baseline: 1.4264x; 1.4264x over previous
#include <cuda_runtime.h>
#include <cuda_bf16.h>

#define VOCAB 100000
#define EMB   300
#define BSZ   2048
#define SEQL  200
#define HID   128
#define OUTD  20

#define EMB4  (EMB / 4)          // 75 float4 per row
#define SPB2  16                 // samples per block in MLP kernel

// rep scratch: [B, EMB] floats (device global — no allocation allowed)
__device__ float4 g_rep4[BSZ * EMB4];

// ---------------------------------------------------------------------------
// Kernel 1: embedding-bag mean.  One thread per (sample, float4 chunk).
// ---------------------------------------------------------------------------
__global__ __launch_bounds__(256) void gather_kernel(
    const int*    __restrict__ x,        // [B, L]
    const int*    __restrict__ lengths,  // [B]
    const float4* __restrict__ emb4)     // [VOCAB, 75]
{
    const int gid = blockIdx.x * 256 + threadIdx.x;
    if (gid >= BSZ * EMB4) return;
    const int b = gid / EMB4;
    const int d = gid - b * EMB4;

    const int* xb = x + (size_t)b * SEQL;

    float4 a0 = make_float4(0.f, 0.f, 0.f, 0.f);
    float4 a1 = a0, a2 = a0, a3 = a0;

    // SEQL = 200, divisible by 4 — no tail
    #pragma unroll 2
    for (int t = 0; t < SEQL; t += 4) {
        const int i0 = __ldg(xb + t + 0);
        const int i1 = __ldg(xb + t + 1);
        const int i2 = __ldg(xb + t + 2);
        const int i3 = __ldg(xb + t + 3);
        const float4 v0 = __ldg(emb4 + (size_t)i0 * EMB4 + d);
        const float4 v1 = __ldg(emb4 + (size_t)i1 * EMB4 + d);
        const float4 v2 = __ldg(emb4 + (size_t)i2 * EMB4 + d);
        const float4 v3 = __ldg(emb4 + (size_t)i3 * EMB4 + d);
        a0.x += v0.x; a0.y += v0.y; a0.z += v0.z; a0.w += v0.w;
        a1.x += v1.x; a1.y += v1.y; a1.z += v1.z; a1.w += v1.w;
        a2.x += v2.x; a2.y += v2.y; a2.z += v2.z; a2.w += v2.w;
        a3.x += v3.x; a3.y += v3.y; a3.z += v3.z; a3.w += v3.w;
    }

    const float inv = 1.0f / (float)__ldg(lengths + b);
    float4 r;
    r.x = (a0.x + a1.x + a2.x + a3.x) * inv;
    r.y = (a0.y + a1.y + a2.y + a3.y) * inv;
    r.z = (a0.z + a1.z + a2.z + a3.z) * inv;
    r.w = (a0.w + a1.w + a2.w + a3.w) * inv;
    g_rep4[gid] = r;
}

// ---------------------------------------------------------------------------
// Kernel 2: logits = relu(rep @ W1 + b1) @ W2 + b2.  16 samples per block.
// ---------------------------------------------------------------------------
__global__ __launch_bounds__(256) void mlp_kernel(
    const float* __restrict__ W1,   // [EMB, HID]
    const float* __restrict__ b1,   // [HID]
    const float* __restrict__ W2,   // [HID, OUTD]
    const float* __restrict__ b2,   // [OUTD]
    float*       __restrict__ out)  // [B, OUTD]
{
    __shared__ float repT[EMB][SPB2];            // 19.2 KB (transposed rep tile)
    __shared__ float hpart[2][SPB2][HID];        // 16 KB
    __shared__ float hbuf[SPB2][HID];            // 8 KB

    const int tid = threadIdx.x;
    const int b0  = blockIdx.x * SPB2;
    const float* rep = (const float*)g_rep4;     // [B, EMB]

    // load rep tile (coalesced gmem read, transpose into smem)
    for (int i = tid; i < SPB2 * EMB; i += 256) {
        const int s = i / EMB;
        const int d = i - s * EMB;
        repT[d][s] = rep[(size_t)(b0 + s) * EMB + d];
    }
    __syncthreads();

    // GEMM1: h[s][j] = sum_d rep[s][d] * W1[d][j]
    {
        const int j  = tid & (HID - 1);
        const int c  = tid >> 7;                 // d-chunk 0/1
        const int d0 = c * 150, d1 = d0 + 150;

        float acc[SPB2];
        #pragma unroll
        for (int s = 0; s < SPB2; ++s) acc[s] = 0.0f;

        for (int d = d0; d < d1; ++d) {
            const float w1 = __ldg(&W1[(size_t)d * HID + j]);
            #pragma unroll
            for (int q = 0; q < SPB2 / 4; ++q) {
                const float4 r = *(const float4*)&repT[d][q * 4];
                acc[q * 4 + 0] += r.x * w1;
                acc[q * 4 + 1] += r.y * w1;
                acc[q * 4 + 2] += r.z * w1;
                acc[q * 4 + 3] += r.w * w1;
            }
        }
        #pragma unroll
        for (int s = 0; s < SPB2; ++s) hpart[c][s][j] = acc[s];
    }
    __syncthreads();

    // combine + bias + relu
    for (int i = tid; i < SPB2 * HID; i += 256) {
        const int s = i >> 7;
        const int j = i & (HID - 1);
        float v = hpart[0][s][j] + hpart[1][s][j] + __ldg(&b1[j]);
        hbuf[s][j] = v > 0.0f ? v : 0.0f;
    }
    __syncthreads();

    // GEMM2: logits[s][o] = sum_k h[s][k] * W2[k][o]
    for (int i = tid; i < SPB2 * OUTD; i += 256) {
        const int s = i / OUTD;
        const int o = i - s * OUTD;
        float acc = __ldg(&b2[o]);
        #pragma unroll 8
        for (int k = 0; k < HID; ++k)
            acc += hbuf[s][k] * __ldg(&W2[(size_t)k * OUTD + o]);
        out[(size_t)(b0 + s) * OUTD + o] = acc;
    }
}

extern "C" void kernel_launch(void* const* d_in, const int* in_sizes, int n_in,
                              void* d_out, int out_size)
{
    const int*    x       = (const int*)    d_in[0];
    const int*    lengths = (const int*)    d_in[1];
    const float4* emb4    = (const float4*) d_in[2];
    const float*  W1      = (const float*)  d_in[3];
    const float*  b1      = (const float*)  d_in[4];
    const float*  W2      = (const float*)  d_in[5];
    const float*  b2      = (const float*)  d_in[6];
    float*        out     = (float*)        d_out;

    const int gather_items = BSZ * EMB4;                   // 153600
    gather_kernel<<<(gather_items + 255) / 256, 256>>>(x, lengths, emb4);
    mlp_kernel<<<BSZ / SPB2, 256>>>(W1, b1, W2, b2, out);
}

// round 3
// speedup vs baseline: 2.4601x; 1.7247x over previous
#include <cuda_runtime.h>
#include <cuda_bf16.h>

#define VOCAB 100000
#define EMB   300
#define BSZ   2048
#define SEQL  200
#define HID   128
#define OUTD  20

#define EMB4  (EMB / 4)          // 75 float4 per row
#define SPB2  8                  // samples per block in MLP kernel -> grid 256

// rep scratch: [B, EMB] floats (device global — no allocation allowed)
__device__ float4 g_rep4[BSZ * EMB4];

// ---------------------------------------------------------------------------
// Kernel 1: embedding-bag mean.  One thread per (sample, float4 chunk).
// 8-way unrolled token loop -> 8 independent gather loads in flight / thread.
// ---------------------------------------------------------------------------
__global__ __launch_bounds__(256) void gather_kernel(
    const int*    __restrict__ x,        // [B, L]
    const int*    __restrict__ lengths,  // [B]
    const float4* __restrict__ emb4)     // [VOCAB, 75]
{
    const int gid = blockIdx.x * 256 + threadIdx.x;
    if (gid >= BSZ * EMB4) return;
    const int b = gid / EMB4;
    const int d = gid - b * EMB4;

    const int4* xb4 = (const int4*)(x + (size_t)b * SEQL);  // 200 ints = 50 int4

    float4 a0 = make_float4(0.f, 0.f, 0.f, 0.f);
    float4 a1 = a0, a2 = a0, a3 = a0, a4 = a0, a5 = a0, a6 = a0, a7 = a0;

    // 200 tokens = 25 iterations x 8 tokens
    #pragma unroll 1
    for (int it = 0; it < 25; ++it) {
        const int4 ia = __ldg(xb4 + it * 2 + 0);
        const int4 ib = __ldg(xb4 + it * 2 + 1);
        const float4 v0 = __ldg(emb4 + (size_t)ia.x * EMB4 + d);
        const float4 v1 = __ldg(emb4 + (size_t)ia.y * EMB4 + d);
        const float4 v2 = __ldg(emb4 + (size_t)ia.z * EMB4 + d);
        const float4 v3 = __ldg(emb4 + (size_t)ia.w * EMB4 + d);
        const float4 v4 = __ldg(emb4 + (size_t)ib.x * EMB4 + d);
        const float4 v5 = __ldg(emb4 + (size_t)ib.y * EMB4 + d);
        const float4 v6 = __ldg(emb4 + (size_t)ib.z * EMB4 + d);
        const float4 v7 = __ldg(emb4 + (size_t)ib.w * EMB4 + d);
        a0.x += v0.x; a0.y += v0.y; a0.z += v0.z; a0.w += v0.w;
        a1.x += v1.x; a1.y += v1.y; a1.z += v1.z; a1.w += v1.w;
        a2.x += v2.x; a2.y += v2.y; a2.z += v2.z; a2.w += v2.w;
        a3.x += v3.x; a3.y += v3.y; a3.z += v3.z; a3.w += v3.w;
        a4.x += v4.x; a4.y += v4.y; a4.z += v4.z; a4.w += v4.w;
        a5.x += v5.x; a5.y += v5.y; a5.z += v5.z; a5.w += v5.w;
        a6.x += v6.x; a6.y += v6.y; a6.z += v6.z; a6.w += v6.w;
        a7.x += v7.x; a7.y += v7.y; a7.z += v7.z; a7.w += v7.w;
    }

    const float inv = 1.0f / (float)__ldg(lengths + b);
    float4 r;
    r.x = (a0.x + a1.x + a2.x + a3.x + a4.x + a5.x + a6.x + a7.x) * inv;
    r.y = (a0.y + a1.y + a2.y + a3.y + a4.y + a5.y + a6.y + a7.y) * inv;
    r.z = (a0.z + a1.z + a2.z + a3.z + a4.z + a5.z + a6.z + a7.z) * inv;
    r.w = (a0.w + a1.w + a2.w + a3.w + a4.w + a5.w + a6.w + a7.w) * inv;
    g_rep4[gid] = r;
}

// ---------------------------------------------------------------------------
// Kernel 2: logits = relu(rep @ W1 + b1) @ W2 + b2.  8 samples per block,
// grid = 256 blocks.
// ---------------------------------------------------------------------------
__global__ __launch_bounds__(256) void mlp_kernel(
    const float* __restrict__ W1,   // [EMB, HID]
    const float* __restrict__ b1,   // [HID]
    const float* __restrict__ W2,   // [HID, OUTD]
    const float* __restrict__ b2,   // [OUTD]
    float*       __restrict__ out)  // [B, OUTD]
{
    __shared__ float repT[EMB][SPB2];            // 9.6 KB (transposed rep tile)
    __shared__ float hpart[2][SPB2][HID];        // 8 KB
    __shared__ float hbuf[SPB2][HID];            // 4 KB

    const int tid = threadIdx.x;
    const int b0  = blockIdx.x * SPB2;
    const float* rep = (const float*)g_rep4;     // [B, EMB]

    // load rep tile (coalesced gmem read, transpose into smem)
    for (int i = tid; i < SPB2 * EMB; i += 256) {
        const int s = i / EMB;
        const int d = i - s * EMB;
        repT[d][s] = rep[(size_t)(b0 + s) * EMB + d];
    }
    __syncthreads();

    // GEMM1: h[s][j] = sum_d rep[s][d] * W1[d][j]; d split in halves of 150
    {
        const int j  = tid & (HID - 1);
        const int c  = tid >> 7;                 // d-chunk 0/1
        const int d0 = c * 150;

        float acc[SPB2];
        #pragma unroll
        for (int s = 0; s < SPB2; ++s) acc[s] = 0.0f;

        // 150 = 6 * 25; unroll 6 with independent W1 loads for pipelining
        #pragma unroll 1
        for (int it = 0; it < 25; ++it) {
            const int d = d0 + it * 6;
            float w[6];
            #pragma unroll
            for (int u = 0; u < 6; ++u)
                w[u] = __ldg(&W1[(size_t)(d + u) * HID + j]);
            #pragma unroll
            for (int u = 0; u < 6; ++u) {
                const float4 r0 = *(const float4*)&repT[d + u][0];
                const float4 r1 = *(const float4*)&repT[d + u][4];
                acc[0] += r0.x * w[u]; acc[1] += r0.y * w[u];
                acc[2] += r0.z * w[u]; acc[3] += r0.w * w[u];
                acc[4] += r1.x * w[u]; acc[5] += r1.y * w[u];
                acc[6] += r1.z * w[u]; acc[7] += r1.w * w[u];
            }
        }
        #pragma unroll
        for (int s = 0; s < SPB2; ++s) hpart[c][s][j] = acc[s];
    }
    __syncthreads();

    // combine + bias + relu
    for (int i = tid; i < SPB2 * HID; i += 256) {
        const int s = i >> 7;
        const int j = i & (HID - 1);
        float v = hpart[0][s][j] + hpart[1][s][j] + __ldg(&b1[j]);
        hbuf[s][j] = v > 0.0f ? v : 0.0f;
    }
    __syncthreads();

    // GEMM2: logits[s][o] = sum_k h[s][k] * W2[k][o]
    for (int i = tid; i < SPB2 * OUTD; i += 256) {
        const int s = i / OUTD;
        const int o = i - s * OUTD;
        float acc = __ldg(&b2[o]);
        #pragma unroll 8
        for (int k = 0; k < HID; ++k)
            acc += hbuf[s][k] * __ldg(&W2[(size_t)k * OUTD + o]);
        out[(size_t)(b0 + s) * OUTD + o] = acc;
    }
}

extern "C" void kernel_launch(void* const* d_in, const int* in_sizes, int n_in,
                              void* d_out, int out_size)
{
    const int*    x       = (const int*)    d_in[0];
    const int*    lengths = (const int*)    d_in[1];
    const float4* emb4    = (const float4*) d_in[2];
    const float*  W1      = (const float*)  d_in[3];
    const float*  b1      = (const float*)  d_in[4];
    const float*  W2      = (const float*)  d_in[5];
    const float*  b2      = (const float*)  d_in[6];
    float*        out     = (float*)        d_out;

    const int gather_items = BSZ * EMB4;                   // 153600
    gather_kernel<<<(gather_items + 255) / 256, 256>>>(x, lengths, emb4);
    mlp_kernel<<<BSZ / SPB2, 256>>>(W1, b1, W2, b2, out);
}